// round 1
// baseline (speedup 1.0000x reference)
#include <cuda_runtime.h>
#include <math.h>

#define NV   65536
#define CH   128
#define NSEGS 1024
#define KT   27
#define NC   (NV*CH)

// ---------------- scratch (device globals; no allocation allowed) ----------
__device__ float g_pw[NC];
__device__ float g_t[NC];
__device__ float g_pf[NC];
__device__ float g_agg[NC];
__device__ float g_fused[NC];
__device__ float g_dbuf[NC];
__device__ float g_ybuf[NC];
__device__ float g_adp[NV*3];
__device__ float g_seg[NSEGS*CH];
__device__ float g_seg2[NSEGS*CH];
__device__ float g_cnt[NSEGS];
__device__ float g_sum[CH];
__device__ float g_sumsq[CH];
__device__ float g_scale[CH];
__device__ float g_bias[CH];
__device__ float g_part[1024];
__device__ float g_gmax[1];

// ---------------- dense GEMM: C[N,128] (+)= A[N,128] @ W[128,128] ----------
__global__ __launch_bounds__(256) void gemm128(const float* __restrict__ A,
                                               const float* __restrict__ W,
                                               float* __restrict__ Cc, int acc)
{
    __shared__ float As[16][128];
    __shared__ float Ws[16][128];
    const int tid = threadIdx.x;
    const int block_row = blockIdx.x * 128;
    const int tx = tid & 15, ty = tid >> 4;
    const int ar = tid >> 1, ac = (tid & 1) * 8;
    const int wr = tid >> 4, wc = (tid & 15) * 8;
    float acc_r[8][8];
#pragma unroll
    for (int i = 0; i < 8; i++)
#pragma unroll
        for (int j = 0; j < 8; j++) acc_r[i][j] = 0.f;

    const float* Arow = A + (size_t)(block_row + ar) * CH;
    for (int k0 = 0; k0 < CH; k0 += 16) {
        float4 a0 = *(const float4*)(Arow + k0 + ac);
        float4 a1 = *(const float4*)(Arow + k0 + ac + 4);
        As[ac + 0][ar] = a0.x; As[ac + 1][ar] = a0.y;
        As[ac + 2][ar] = a0.z; As[ac + 3][ar] = a0.w;
        As[ac + 4][ar] = a1.x; As[ac + 5][ar] = a1.y;
        As[ac + 6][ar] = a1.z; As[ac + 7][ar] = a1.w;
        const float* Wp = W + (size_t)(k0 + wr) * CH + wc;
        *(float4*)&Ws[wr][wc]     = *(const float4*)Wp;
        *(float4*)&Ws[wr][wc + 4] = *(const float4*)(Wp + 4);
        __syncthreads();
#pragma unroll
        for (int kk = 0; kk < 16; kk++) {
            float af[8], wf[8];
            *(float4*)(af)     = *(const float4*)&As[kk][ty * 8];
            *(float4*)(af + 4) = *(const float4*)&As[kk][ty * 8 + 4];
            *(float4*)(wf)     = *(const float4*)&Ws[kk][tx * 8];
            *(float4*)(wf + 4) = *(const float4*)&Ws[kk][tx * 8 + 4];
#pragma unroll
            for (int i = 0; i < 8; i++)
#pragma unroll
                for (int j = 0; j < 8; j++)
                    acc_r[i][j] += af[i] * wf[j];
        }
        __syncthreads();
    }
#pragma unroll
    for (int i = 0; i < 8; i++) {
        float* Cp = Cc + (size_t)(block_row + ty * 8 + i) * CH + tx * 8;
        float4 c0, c1;
        c0.x = acc_r[i][0]; c0.y = acc_r[i][1]; c0.z = acc_r[i][2]; c0.w = acc_r[i][3];
        c1.x = acc_r[i][4]; c1.y = acc_r[i][5]; c1.z = acc_r[i][6]; c1.w = acc_r[i][7];
        if (acc) {
            float4 o0 = *(const float4*)Cp, o1 = *(const float4*)(Cp + 4);
            c0.x += o0.x; c0.y += o0.y; c0.z += o0.z; c0.w += o0.w;
            c1.x += o1.x; c1.y += o1.y; c1.z += o1.z; c1.w += o1.w;
        }
        *(float4*)Cp = c0; *(float4*)(Cp + 4) = c1;
    }
}

// -------- sparse conv: Out[n,:] = sum_k (mask? X[idx[n,k],:] : 0) @ W[k] ----
__global__ __launch_bounds__(256) void sconv128(const float* __restrict__ X,
                                                const int* __restrict__ nbr,
                                                const float* __restrict__ W,
                                                float* __restrict__ Out)
{
    __shared__ float As[16][128];
    __shared__ float Ws[16][128];
    __shared__ int nid[128];
    const int tid = threadIdx.x;
    const int block_row = blockIdx.x * 128;
    const int tx = tid & 15, ty = tid >> 4;
    const int ar = tid >> 1, ac = (tid & 1) * 8;
    const int wr = tid >> 4, wc = (tid & 15) * 8;
    float acc_r[8][8];
#pragma unroll
    for (int i = 0; i < 8; i++)
#pragma unroll
        for (int j = 0; j < 8; j++) acc_r[i][j] = 0.f;

    for (int k = 0; k < KT; k++) {
        if (tid < 128) nid[tid] = nbr[(size_t)(block_row + tid) * KT + k];
        __syncthreads();
        const int nrow = nid[ar];
        const bool valid = (nrow < NV);
        const float* Xrow = X + (size_t)(valid ? nrow : 0) * CH;
        const float* Wk = W + (size_t)k * CH * CH;
        for (int k0 = 0; k0 < CH; k0 += 16) {
            float4 a0, a1;
            if (valid) {
                a0 = *(const float4*)(Xrow + k0 + ac);
                a1 = *(const float4*)(Xrow + k0 + ac + 4);
            } else {
                a0 = make_float4(0.f, 0.f, 0.f, 0.f); a1 = a0;
            }
            As[ac + 0][ar] = a0.x; As[ac + 1][ar] = a0.y;
            As[ac + 2][ar] = a0.z; As[ac + 3][ar] = a0.w;
            As[ac + 4][ar] = a1.x; As[ac + 5][ar] = a1.y;
            As[ac + 6][ar] = a1.z; As[ac + 7][ar] = a1.w;
            const float* Wp = Wk + (size_t)(k0 + wr) * CH + wc;
            *(float4*)&Ws[wr][wc]     = *(const float4*)Wp;
            *(float4*)&Ws[wr][wc + 4] = *(const float4*)(Wp + 4);
            __syncthreads();
#pragma unroll
            for (int kk = 0; kk < 16; kk++) {
                float af[8], wf[8];
                *(float4*)(af)     = *(const float4*)&As[kk][ty * 8];
                *(float4*)(af + 4) = *(const float4*)&As[kk][ty * 8 + 4];
                *(float4*)(wf)     = *(const float4*)&Ws[kk][tx * 8];
                *(float4*)(wf + 4) = *(const float4*)&Ws[kk][tx * 8 + 4];
#pragma unroll
                for (int i = 0; i < 8; i++)
#pragma unroll
                    for (int j = 0; j < 8; j++)
                        acc_r[i][j] += af[i] * wf[j];
            }
            __syncthreads();
        }
    }
#pragma unroll
    for (int i = 0; i < 8; i++) {
        float* Cp = Out + (size_t)(block_row + ty * 8 + i) * CH + tx * 8;
        float4 c0, c1;
        c0.x = acc_r[i][0]; c0.y = acc_r[i][1]; c0.z = acc_r[i][2]; c0.w = acc_r[i][3];
        c1.x = acc_r[i][4]; c1.y = acc_r[i][5]; c1.z = acc_r[i][6]; c1.w = acc_r[i][7];
        *(float4*)Cp = c0; *(float4*)(Cp + 4) = c1;
    }
}

// ---------------- BN stats / finalize / apply -------------------------------
__global__ void colstats(const float* __restrict__ X, float* __restrict__ sum,
                         float* __restrict__ sumsq)
{
    const int rstart = blockIdx.x * 128;
    const int t = threadIdx.x;
    float s = 0.f, q = 0.f;
    const float* p = X + (size_t)rstart * CH + t;
    for (int r = 0; r < 128; r++) {
        float v = p[(size_t)r * CH];
        s += v; q += v * v;
    }
    atomicAdd(&sum[t], s);
    atomicAdd(&sumsq[t], q);
}

__global__ void bn_finalize(const float* __restrict__ sum, const float* __restrict__ sumsq,
                            const float* __restrict__ gamma, const float* __restrict__ beta,
                            float* __restrict__ scale, float* __restrict__ bias)
{
    int c = threadIdx.x;
    float m = sum[c] * (1.f / (float)NV);
    float v = sumsq[c] * (1.f / (float)NV) - m * m;
    float sc = gamma[c] * rsqrtf(v + 1e-5f);
    scale[c] = sc;
    bias[c] = beta[c] - m * sc;
}

// mode 0: lrelu(a*x+b); mode 1: lrelu(a*x+b)+res; mode 2: lrelu(a*x+b+res)
__global__ void bn_act(const float* __restrict__ X, const float* __restrict__ scale,
                       const float* __restrict__ bias, const float* __restrict__ res,
                       float* __restrict__ Y, int mode)
{
    int i = blockIdx.x * blockDim.x + threadIdx.x;
    int c = i & 127;
    float v = X[i] * scale[c] + bias[c];
    if (mode == 2) v += res[i];
    v = (v >= 0.f) ? v : 0.01f * v;
    if (mode == 1) v += res[i];
    Y[i] = v;
}

// ---------------- segment ops ----------------------------------------------
__global__ void seg_count(const int* __restrict__ cl, float* __restrict__ cnt)
{
    int i = blockIdx.x * blockDim.x + threadIdx.x;
    atomicAdd(&cnt[cl[i]], 1.f);
}

__global__ void seg_sum(const float* __restrict__ X, const int* __restrict__ cl,
                        float* __restrict__ S)
{
    int i = blockIdx.x * blockDim.x + threadIdx.x;
    int n = i >> 7, c = i & 127;
    atomicAdd(&S[(size_t)cl[n] * CH + c], X[i]);
}

__global__ void sub_segmean(float* __restrict__ X, const float* __restrict__ S,
                            const float* __restrict__ cnt, const int* __restrict__ cl)
{
    int i = blockIdx.x * blockDim.x + threadIdx.x;
    int n = i >> 7, c = i & 127;
    int s = cl[n];
    X[i] -= S[(size_t)s * CH + c] / fmaxf(cnt[s], 1.f);
}

__global__ void weight_mul(float* __restrict__ PF, const float* __restrict__ T,
                           const float* __restrict__ S, const int* __restrict__ cl)
{
    int i = blockIdx.x * blockDim.x + threadIdx.x;
    int n = i >> 7, c = i & 127;
    PF[i] *= T[i] / (S[(size_t)cl[n] * CH + c] + 1e-6f);
}

__global__ void agg_acc(float* __restrict__ AGG, const float* __restrict__ adp, int lvl,
                        const float* __restrict__ S, const int* __restrict__ cl)
{
    int i = blockIdx.x * blockDim.x + threadIdx.x;
    int n = i >> 7, c = i & 127;
    AGG[i] += adp[n * 3 + lvl] * S[(size_t)cl[n] * CH + c];
}

// ---------------- global max (two stage) ------------------------------------
__global__ void rmax1(const float* __restrict__ X, float* __restrict__ part)
{
    __shared__ float sm[256];
    float m = -3.4e38f;
    for (int i = blockIdx.x * 256 + threadIdx.x; i < NC; i += gridDim.x * 256)
        m = fmaxf(m, X[i]);
    sm[threadIdx.x] = m;
    __syncthreads();
    for (int o = 128; o; o >>= 1) {
        if (threadIdx.x < o) sm[threadIdx.x] = fmaxf(sm[threadIdx.x], sm[threadIdx.x + o]);
        __syncthreads();
    }
    if (threadIdx.x == 0) part[blockIdx.x] = sm[0];
}

__global__ void rmax2(const float* __restrict__ part, float* __restrict__ out)
{
    __shared__ float sm[256];
    float m = -3.4e38f;
    for (int i = threadIdx.x; i < 1024; i += 256) m = fmaxf(m, part[i]);
    sm[threadIdx.x] = m;
    __syncthreads();
    for (int o = 128; o; o >>= 1) {
        if (threadIdx.x < o) sm[threadIdx.x] = fmaxf(sm[threadIdx.x], sm[threadIdx.x + o]);
        __syncthreads();
    }
    if (threadIdx.x == 0) out[0] = sm[0];
}

// ---------------- exp shift --------------------------------------------------
__global__ void exp_shift(float* __restrict__ T, const float* __restrict__ gmax)
{
    int i = blockIdx.x * blockDim.x + threadIdx.x;
    T[i] = expf(T[i] - gmax[0]);
}

// ---------------- adaptive softmax (feat @ [128,3] -> softmax) ---------------
__global__ void adp_kernel(const float* __restrict__ feat, const float* __restrict__ aw,
                           float* __restrict__ adp)
{
    int row = blockIdx.x * 8 + (threadIdx.x >> 5);
    int lane = threadIdx.x & 31;
    float d0 = 0.f, d1 = 0.f, d2 = 0.f;
    const float* f = feat + (size_t)row * CH;
#pragma unroll
    for (int j = lane; j < CH; j += 32) {
        float v = f[j];
        d0 += v * aw[j * 3 + 0];
        d1 += v * aw[j * 3 + 1];
        d2 += v * aw[j * 3 + 2];
    }
#pragma unroll
    for (int o = 16; o; o >>= 1) {
        d0 += __shfl_xor_sync(0xffffffffu, d0, o);
        d1 += __shfl_xor_sync(0xffffffffu, d1, o);
        d2 += __shfl_xor_sync(0xffffffffu, d2, o);
    }
    if (lane == 0) {
        float m = fmaxf(d0, fmaxf(d1, d2));
        float e0 = expf(d0 - m), e1 = expf(d1 - m), e2 = expf(d2 - m);
        float inv = 1.f / (e0 + e1 + e2);
        adp[row * 3 + 0] = e0 * inv;
        adp[row * 3 + 1] = e1 * inv;
        adp[row * 3 + 2] = e2 * inv;
    }
}

// ---------------- orchestration ----------------------------------------------
extern "C" void kernel_launch(void* const* d_in, const int* in_sizes, int n_in,
                              void* d_out, int out_size)
{
    const float* feat       = (const float*)d_in[0];
    const int*   clusters   = (const int*)d_in[1];
    const int*   nbr        = (const int*)d_in[2];
    const float* lw_w       = (const float*)d_in[3];
    const float* lw_gamma   = (const float*)d_in[4];
    const float* lw_beta    = (const float*)d_in[5];
    const float* w_w        = (const float*)d_in[6];
    const float* proj_w     = (const float*)d_in[7];
    const float* proj_gamma = (const float*)d_in[8];
    const float* proj_beta  = (const float*)d_in[9];
    const float* adaptive_w = (const float*)d_in[10];
    const float* fuse_w     = (const float*)d_in[11];
    const float* fuse_gamma = (const float*)d_in[12];
    const float* fuse_beta  = (const float*)d_in[13];
    const float* conv1_w    = (const float*)d_in[14];
    const float* conv2_w    = (const float*)d_in[15];
    const float* bn1_gamma  = (const float*)d_in[16];
    const float* bn1_beta   = (const float*)d_in[17];
    const float* bn2_gamma  = (const float*)d_in[18];
    const float* bn2_beta   = (const float*)d_in[19];
    float* out = (float*)d_out;

    float *pw, *t, *pf, *agg, *fused, *dbuf, *ybuf, *adp, *seg, *seg2, *cnt;
    float *sum, *sumsq, *scale, *bias, *part, *gmax;
    cudaGetSymbolAddress((void**)&pw, g_pw);
    cudaGetSymbolAddress((void**)&t, g_t);
    cudaGetSymbolAddress((void**)&pf, g_pf);
    cudaGetSymbolAddress((void**)&agg, g_agg);
    cudaGetSymbolAddress((void**)&fused, g_fused);
    cudaGetSymbolAddress((void**)&dbuf, g_dbuf);
    cudaGetSymbolAddress((void**)&ybuf, g_ybuf);
    cudaGetSymbolAddress((void**)&adp, g_adp);
    cudaGetSymbolAddress((void**)&seg, g_seg);
    cudaGetSymbolAddress((void**)&seg2, g_seg2);
    cudaGetSymbolAddress((void**)&cnt, g_cnt);
    cudaGetSymbolAddress((void**)&sum, g_sum);
    cudaGetSymbolAddress((void**)&sumsq, g_sumsq);
    cudaGetSymbolAddress((void**)&scale, g_scale);
    cudaGetSymbolAddress((void**)&bias, g_bias);
    cudaGetSymbolAddress((void**)&part, g_part);
    cudaGetSymbolAddress((void**)&gmax, g_gmax);

    const int EB = 256;
    const int EG = NC / EB;

    auto bn_pipeline = [&](const float* X, const float* gamma, const float* beta) {
        cudaMemsetAsync(sum, 0, CH * sizeof(float), 0);
        cudaMemsetAsync(sumsq, 0, CH * sizeof(float), 0);
        colstats<<<NV / 128, 128>>>(X, sum, sumsq);
        bn_finalize<<<1, 128>>>(sum, sumsq, gamma, beta, scale, bias);
    };

    cudaMemsetAsync(agg, 0, (size_t)NC * sizeof(float), 0);
    adp_kernel<<<NV / 8, 256>>>(feat, adaptive_w, adp);

    for (int i = 0; i < 3; i++) {
        const int* cl = clusters + (size_t)i * NV;
        // pw = lrelu(bn(feat @ lw_w[i]))
        gemm128<<<512, 256>>>(feat, lw_w + (size_t)i * CH * CH, pw, 0);
        bn_pipeline(pw, lw_gamma + i * CH, lw_beta + i * CH);
        bn_act<<<EG, EB>>>(pw, scale, bias, nullptr, pw, 0);
        // per-cluster centering
        cudaMemsetAsync(cnt, 0, NSEGS * sizeof(float), 0);
        cudaMemsetAsync(seg, 0, (size_t)NSEGS * CH * sizeof(float), 0);
        seg_count<<<NV / 256, 256>>>(cl, cnt);
        seg_sum<<<EG, EB>>>(pw, cl, seg);
        sub_segmean<<<EG, EB>>>(pw, seg, cnt, cl);
        // attention logits -> exp(global-max-shifted) -> per-cluster normalize
        gemm128<<<512, 256>>>(pw, w_w + (size_t)i * CH * CH, t, 0);
        rmax1<<<1024, 256>>>(t, part);
        rmax2<<<1, 256>>>(part, gmax);
        exp_shift<<<EG, EB>>>(t, gmax);
        cudaMemsetAsync(seg, 0, (size_t)NSEGS * CH * sizeof(float), 0);
        seg_sum<<<EG, EB>>>(t, cl, seg);
        // pf = lrelu(bn(feat @ proj_w[i])) * weights ; segment-sum ; agg accumulate
        gemm128<<<512, 256>>>(feat, proj_w + (size_t)i * CH * CH, pf, 0);
        bn_pipeline(pf, proj_gamma + i * CH, proj_beta + i * CH);
        bn_act<<<EG, EB>>>(pf, scale, bias, nullptr, pf, 0);
        weight_mul<<<EG, EB>>>(pf, t, seg, cl);
        cudaMemsetAsync(seg2, 0, (size_t)NSEGS * CH * sizeof(float), 0);
        seg_sum<<<EG, EB>>>(pf, cl, seg2);
        agg_acc<<<EG, EB>>>(agg, adp, i, seg2, cl);
    }

    // f_last = lrelu(bn(feat @ proj_w[3]))
    gemm128<<<512, 256>>>(feat, proj_w + (size_t)3 * CH * CH, pf, 0);
    bn_pipeline(pf, proj_gamma + 3 * CH, proj_beta + 3 * CH);
    bn_act<<<EG, EB>>>(pf, scale, bias, nullptr, pf, 0);

    // fused = lrelu(bn([f_last, agg] @ fuse_w)) + feat
    gemm128<<<512, 256>>>(pf, fuse_w, t, 0);
    gemm128<<<512, 256>>>(agg, fuse_w + (size_t)CH * CH, t, 1);
    bn_pipeline(t, fuse_gamma, fuse_beta);
    bn_act<<<EG, EB>>>(t, scale, bias, feat, fused, 1);

    // conv1 -> bn1 -> lrelu
    sconv128<<<512, 256>>>(fused, nbr, conv1_w, ybuf);
    bn_pipeline(ybuf, bn1_gamma, bn1_beta);
    bn_act<<<EG, EB>>>(ybuf, scale, bias, nullptr, dbuf, 0);

    // conv2 -> bn2 (+ residual) -> lrelu
    sconv128<<<512, 256>>>(dbuf, nbr, conv2_w, ybuf);
    bn_pipeline(ybuf, bn2_gamma, bn2_beta);
    bn_act<<<EG, EB>>>(ybuf, scale, bias, fused, out, 2);
}

// round 2
// speedup vs baseline: 1.0631x; 1.0631x over previous
#include <cuda_runtime.h>
#include <math.h>

#define NV   65536
#define CH   128
#define NSEGS 1024
#define KT   27
#define NC   (NV*CH)

typedef unsigned long long u64;

__device__ __forceinline__ u64 pk2(float x) {
    u64 r; asm("mov.b64 %0, {%1, %1};" : "=l"(r) : "f"(x)); return r;
}
__device__ __forceinline__ void fma2(u64 &d, u64 a, u64 b) {
    asm("fma.rn.f32x2 %0, %1, %2, %0;" : "+l"(d) : "l"(a), "l"(b));
}
__device__ __forceinline__ float2 upk(u64 v) {
    float2 f; asm("mov.b64 {%0, %1}, %2;" : "=f"(f.x), "=f"(f.y) : "l"(v)); return f;
}

// ---------------- scratch (device globals; no allocation allowed) ----------
__device__ float g_pw[NC];
__device__ float g_t[NC];
__device__ float g_pf[NC];
__device__ float g_agg[NC];
__device__ float g_fused[NC];
__device__ float g_dbuf[NC];
__device__ float g_ybuf[NC];
__device__ float g_adp[NV*3];
__device__ float g_seg[NSEGS*CH];
__device__ float g_seg2[NSEGS*CH];
__device__ float g_cnt[NSEGS];
__device__ float g_sum[CH];
__device__ float g_sumsq[CH];
__device__ float g_scale[CH];
__device__ float g_bias[CH];
__device__ float g_part[1024];
__device__ float g_gmax[1];

// ---------------- dense GEMM: C[N,128] (+)= A[N,128] @ W[128,128] ----------
// packed f32x2 inner product: each thread owns 8 rows x 8 cols = 8x4 f32x2 accum
__global__ __launch_bounds__(256, 2) void gemm128(const float* __restrict__ A,
                                                  const float* __restrict__ W,
                                                  float* __restrict__ Cc, int acc)
{
    __shared__ float As[16][128];
    __shared__ float Ws[16][128];
    const int tid = threadIdx.x;
    const int block_row = blockIdx.x * 128;
    const int tx = tid & 15, ty = tid >> 4;
    const int ar = tid >> 1, ac = (tid & 1) * 8;
    const int wr = tid >> 4, wc = (tid & 15) * 8;
    u64 acc2[8][4];
#pragma unroll
    for (int i = 0; i < 8; i++)
#pragma unroll
        for (int j = 0; j < 4; j++) acc2[i][j] = 0ull;

    const float* Arow = A + (size_t)(block_row + ar) * CH;
#pragma unroll 1
    for (int k0 = 0; k0 < CH; k0 += 16) {
        float4 a0 = *(const float4*)(Arow + k0 + ac);
        float4 a1 = *(const float4*)(Arow + k0 + ac + 4);
        As[ac + 0][ar] = a0.x; As[ac + 1][ar] = a0.y;
        As[ac + 2][ar] = a0.z; As[ac + 3][ar] = a0.w;
        As[ac + 4][ar] = a1.x; As[ac + 5][ar] = a1.y;
        As[ac + 6][ar] = a1.z; As[ac + 7][ar] = a1.w;
        const float* Wp = W + (size_t)(k0 + wr) * CH + wc;
        *(float4*)&Ws[wr][wc]     = *(const float4*)Wp;
        *(float4*)&Ws[wr][wc + 4] = *(const float4*)(Wp + 4);
        __syncthreads();
#pragma unroll
        for (int kk = 0; kk < 16; kk++) {
            float4 a0r = *(const float4*)&As[kk][ty * 8];
            float4 a1r = *(const float4*)&As[kk][ty * 8 + 4];
            double2 wq0 = *(const double2*)&Ws[kk][tx * 8];
            double2 wq1 = *(const double2*)&Ws[kk][tx * 8 + 4];
            u64 w0 = __double_as_longlong(wq0.x);
            u64 w1 = __double_as_longlong(wq0.y);
            u64 w2 = __double_as_longlong(wq1.x);
            u64 w3 = __double_as_longlong(wq1.y);
            u64 av[8];
            av[0] = pk2(a0r.x); av[1] = pk2(a0r.y); av[2] = pk2(a0r.z); av[3] = pk2(a0r.w);
            av[4] = pk2(a1r.x); av[5] = pk2(a1r.y); av[6] = pk2(a1r.z); av[7] = pk2(a1r.w);
#pragma unroll
            for (int i = 0; i < 8; i++) {
                fma2(acc2[i][0], av[i], w0);
                fma2(acc2[i][1], av[i], w1);
                fma2(acc2[i][2], av[i], w2);
                fma2(acc2[i][3], av[i], w3);
            }
        }
        __syncthreads();
    }
#pragma unroll
    for (int i = 0; i < 8; i++) {
        float* Cp = Cc + (size_t)(block_row + ty * 8 + i) * CH + tx * 8;
        float2 p0 = upk(acc2[i][0]), p1 = upk(acc2[i][1]);
        float2 p2 = upk(acc2[i][2]), p3 = upk(acc2[i][3]);
        float4 c0 = make_float4(p0.x, p0.y, p1.x, p1.y);
        float4 c1 = make_float4(p2.x, p2.y, p3.x, p3.y);
        if (acc) {
            float4 o0 = *(const float4*)Cp, o1 = *(const float4*)(Cp + 4);
            c0.x += o0.x; c0.y += o0.y; c0.z += o0.z; c0.w += o0.w;
            c1.x += o1.x; c1.y += o1.y; c1.z += o1.z; c1.w += o1.w;
        }
        *(float4*)Cp = c0; *(float4*)(Cp + 4) = c1;
    }
}

// -------- sparse conv: Out[n,:] = sum_k (mask? X[idx[n,k],:] : 0) @ W[k] ----
__global__ __launch_bounds__(256, 2) void sconv128(const float* __restrict__ X,
                                                   const int* __restrict__ nbr,
                                                   const float* __restrict__ W,
                                                   float* __restrict__ Out)
{
    __shared__ float As[32][128];
    __shared__ float Ws[32][128];
    __shared__ int nid[128];
    const int tid = threadIdx.x;
    const int block_row = blockIdx.x * 128;
    const int tx = tid & 15, ty = tid >> 4;
    const int ar = tid >> 1, ac = (tid & 1) * 8;
    const int wr = tid >> 4, wc = (tid & 15) * 8;
    u64 acc2[8][4];
#pragma unroll
    for (int i = 0; i < 8; i++)
#pragma unroll
        for (int j = 0; j < 4; j++) acc2[i][j] = 0ull;

#pragma unroll 1
    for (int k = 0; k < KT; k++) {
        if (tid < 128) nid[tid] = nbr[(size_t)(block_row + tid) * KT + k];
        __syncthreads();
        const int nrow = nid[ar];
        const bool valid = (nrow < NV);
        const float* Xrow = X + (size_t)(valid ? nrow : 0) * CH;
        const float* Wk = W + (size_t)k * CH * CH;
#pragma unroll 1
        for (int k0 = 0; k0 < CH; k0 += 32) {
#pragma unroll
            for (int s = 0; s < 2; s++) {
                const int cb = k0 + s * 16 + ac;
                float4 a0, a1;
                if (valid) {
                    a0 = *(const float4*)(Xrow + cb);
                    a1 = *(const float4*)(Xrow + cb + 4);
                } else {
                    a0 = make_float4(0.f, 0.f, 0.f, 0.f); a1 = a0;
                }
                const int rb = s * 16 + ac;
                As[rb + 0][ar] = a0.x; As[rb + 1][ar] = a0.y;
                As[rb + 2][ar] = a0.z; As[rb + 3][ar] = a0.w;
                As[rb + 4][ar] = a1.x; As[rb + 5][ar] = a1.y;
                As[rb + 6][ar] = a1.z; As[rb + 7][ar] = a1.w;
                const float* Wp = Wk + (size_t)(k0 + s * 16 + wr) * CH + wc;
                *(float4*)&Ws[s * 16 + wr][wc]     = *(const float4*)Wp;
                *(float4*)&Ws[s * 16 + wr][wc + 4] = *(const float4*)(Wp + 4);
            }
            __syncthreads();
#pragma unroll
            for (int kk = 0; kk < 32; kk++) {
                float4 a0r = *(const float4*)&As[kk][ty * 8];
                float4 a1r = *(const float4*)&As[kk][ty * 8 + 4];
                double2 wq0 = *(const double2*)&Ws[kk][tx * 8];
                double2 wq1 = *(const double2*)&Ws[kk][tx * 8 + 4];
                u64 w0 = __double_as_longlong(wq0.x);
                u64 w1 = __double_as_longlong(wq0.y);
                u64 w2 = __double_as_longlong(wq1.x);
                u64 w3 = __double_as_longlong(wq1.y);
                u64 av[8];
                av[0] = pk2(a0r.x); av[1] = pk2(a0r.y); av[2] = pk2(a0r.z); av[3] = pk2(a0r.w);
                av[4] = pk2(a1r.x); av[5] = pk2(a1r.y); av[6] = pk2(a1r.z); av[7] = pk2(a1r.w);
#pragma unroll
                for (int i = 0; i < 8; i++) {
                    fma2(acc2[i][0], av[i], w0);
                    fma2(acc2[i][1], av[i], w1);
                    fma2(acc2[i][2], av[i], w2);
                    fma2(acc2[i][3], av[i], w3);
                }
            }
            __syncthreads();
        }
    }
#pragma unroll
    for (int i = 0; i < 8; i++) {
        float* Cp = Out + (size_t)(block_row + ty * 8 + i) * CH + tx * 8;
        float2 p0 = upk(acc2[i][0]), p1 = upk(acc2[i][1]);
        float2 p2 = upk(acc2[i][2]), p3 = upk(acc2[i][3]);
        *(float4*)Cp       = make_float4(p0.x, p0.y, p1.x, p1.y);
        *(float4*)(Cp + 4) = make_float4(p2.x, p2.y, p3.x, p3.y);
    }
}

// ---------------- BN stats / finalize / apply -------------------------------
__global__ void colstats(const float* __restrict__ X, float* __restrict__ sum,
                         float* __restrict__ sumsq)
{
    const int rstart = blockIdx.x * 128;
    const int t = threadIdx.x;
    float s = 0.f, q = 0.f;
    const float* p = X + (size_t)rstart * CH + t;
    for (int r = 0; r < 128; r++) {
        float v = p[(size_t)r * CH];
        s += v; q += v * v;
    }
    atomicAdd(&sum[t], s);
    atomicAdd(&sumsq[t], q);
}

__global__ void bn_finalize(const float* __restrict__ sum, const float* __restrict__ sumsq,
                            const float* __restrict__ gamma, const float* __restrict__ beta,
                            float* __restrict__ scale, float* __restrict__ bias)
{
    int c = threadIdx.x;
    float m = sum[c] * (1.f / (float)NV);
    float v = sumsq[c] * (1.f / (float)NV) - m * m;
    float sc = gamma[c] * rsqrtf(v + 1e-5f);
    scale[c] = sc;
    bias[c] = beta[c] - m * sc;
}

// mode 0: lrelu(a*x+b); mode 1: lrelu(a*x+b)+res; mode 2: lrelu(a*x+b+res)
__global__ void bn_act(const float* __restrict__ X, const float* __restrict__ scale,
                       const float* __restrict__ bias, const float* __restrict__ res,
                       float* __restrict__ Y, int mode)
{
    int i = blockIdx.x * blockDim.x + threadIdx.x;
    int c = i & 127;
    float v = X[i] * scale[c] + bias[c];
    if (mode == 2) v += res[i];
    v = (v >= 0.f) ? v : 0.01f * v;
    if (mode == 1) v += res[i];
    Y[i] = v;
}

// ---------------- segment ops ----------------------------------------------
__global__ void seg_count(const int* __restrict__ cl, float* __restrict__ cnt)
{
    int i = blockIdx.x * blockDim.x + threadIdx.x;
    atomicAdd(&cnt[cl[i]], 1.f);
}

__global__ void seg_sum(const float* __restrict__ X, const int* __restrict__ cl,
                        float* __restrict__ S)
{
    int i = blockIdx.x * blockDim.x + threadIdx.x;
    int n = i >> 7, c = i & 127;
    atomicAdd(&S[(size_t)cl[n] * CH + c], X[i]);
}

__global__ void sub_segmean(float* __restrict__ X, const float* __restrict__ S,
                            const float* __restrict__ cnt, const int* __restrict__ cl)
{
    int i = blockIdx.x * blockDim.x + threadIdx.x;
    int n = i >> 7, c = i & 127;
    int s = cl[n];
    X[i] -= S[(size_t)s * CH + c] / fmaxf(cnt[s], 1.f);
}

// fused: t = exp(t - gmax); atomicAdd into seg
__global__ void exp_seg(float* __restrict__ T, const float* __restrict__ gmax,
                        const int* __restrict__ cl, float* __restrict__ S)
{
    int i = blockIdx.x * blockDim.x + threadIdx.x;
    int n = i >> 7, c = i & 127;
    float e = expf(T[i] - gmax[0]);
    T[i] = e;
    atomicAdd(&S[(size_t)cl[n] * CH + c], e);
}

// fused: pf *= t / (seg[cl]+eps); atomicAdd into seg2
__global__ void wmul_seg(float* __restrict__ PF, const float* __restrict__ T,
                         const float* __restrict__ S, const int* __restrict__ cl,
                         float* __restrict__ S2)
{
    int i = blockIdx.x * blockDim.x + threadIdx.x;
    int n = i >> 7, c = i & 127;
    int s = cl[n];
    float v = PF[i] * (T[i] / (S[(size_t)s * CH + c] + 1e-6f));
    PF[i] = v;
    atomicAdd(&S2[(size_t)s * CH + c], v);
}

__global__ void agg_acc(float* __restrict__ AGG, const float* __restrict__ adp, int lvl,
                        const float* __restrict__ S, const int* __restrict__ cl)
{
    int i = blockIdx.x * blockDim.x + threadIdx.x;
    int n = i >> 7, c = i & 127;
    AGG[i] += adp[n * 3 + lvl] * S[(size_t)cl[n] * CH + c];
}

// ---------------- global max (two stage) ------------------------------------
__global__ void rmax1(const float* __restrict__ X, float* __restrict__ part)
{
    __shared__ float sm[256];
    float m = -3.4e38f;
    for (int i = blockIdx.x * 256 + threadIdx.x; i < NC; i += gridDim.x * 256)
        m = fmaxf(m, X[i]);
    sm[threadIdx.x] = m;
    __syncthreads();
    for (int o = 128; o; o >>= 1) {
        if (threadIdx.x < o) sm[threadIdx.x] = fmaxf(sm[threadIdx.x], sm[threadIdx.x + o]);
        __syncthreads();
    }
    if (threadIdx.x == 0) part[blockIdx.x] = sm[0];
}

__global__ void rmax2(const float* __restrict__ part, float* __restrict__ out)
{
    __shared__ float sm[256];
    float m = -3.4e38f;
    for (int i = threadIdx.x; i < 1024; i += 256) m = fmaxf(m, part[i]);
    sm[threadIdx.x] = m;
    __syncthreads();
    for (int o = 128; o; o >>= 1) {
        if (threadIdx.x < o) sm[threadIdx.x] = fmaxf(sm[threadIdx.x], sm[threadIdx.x + o]);
        __syncthreads();
    }
    if (threadIdx.x == 0) out[0] = sm[0];
}

// ---------------- adaptive softmax (feat @ [128,3] -> softmax) ---------------
__global__ void adp_kernel(const float* __restrict__ feat, const float* __restrict__ aw,
                           float* __restrict__ adp)
{
    int row = blockIdx.x * 8 + (threadIdx.x >> 5);
    int lane = threadIdx.x & 31;
    float d0 = 0.f, d1 = 0.f, d2 = 0.f;
    const float* f = feat + (size_t)row * CH;
#pragma unroll
    for (int j = lane; j < CH; j += 32) {
        float v = f[j];
        d0 += v * aw[j * 3 + 0];
        d1 += v * aw[j * 3 + 1];
        d2 += v * aw[j * 3 + 2];
    }
#pragma unroll
    for (int o = 16; o; o >>= 1) {
        d0 += __shfl_xor_sync(0xffffffffu, d0, o);
        d1 += __shfl_xor_sync(0xffffffffu, d1, o);
        d2 += __shfl_xor_sync(0xffffffffu, d2, o);
    }
    if (lane == 0) {
        float m = fmaxf(d0, fmaxf(d1, d2));
        float e0 = expf(d0 - m), e1 = expf(d1 - m), e2 = expf(d2 - m);
        float inv = 1.f / (e0 + e1 + e2);
        adp[row * 3 + 0] = e0 * inv;
        adp[row * 3 + 1] = e1 * inv;
        adp[row * 3 + 2] = e2 * inv;
    }
}

// ---------------- orchestration ----------------------------------------------
extern "C" void kernel_launch(void* const* d_in, const int* in_sizes, int n_in,
                              void* d_out, int out_size)
{
    const float* feat       = (const float*)d_in[0];
    const int*   clusters   = (const int*)d_in[1];
    const int*   nbr        = (const int*)d_in[2];
    const float* lw_w       = (const float*)d_in[3];
    const float* lw_gamma   = (const float*)d_in[4];
    const float* lw_beta    = (const float*)d_in[5];
    const float* w_w        = (const float*)d_in[6];
    const float* proj_w     = (const float*)d_in[7];
    const float* proj_gamma = (const float*)d_in[8];
    const float* proj_beta  = (const float*)d_in[9];
    const float* adaptive_w = (const float*)d_in[10];
    const float* fuse_w     = (const float*)d_in[11];
    const float* fuse_gamma = (const float*)d_in[12];
    const float* fuse_beta  = (const float*)d_in[13];
    const float* conv1_w    = (const float*)d_in[14];
    const float* conv2_w    = (const float*)d_in[15];
    const float* bn1_gamma  = (const float*)d_in[16];
    const float* bn1_beta   = (const float*)d_in[17];
    const float* bn2_gamma  = (const float*)d_in[18];
    const float* bn2_beta   = (const float*)d_in[19];
    float* out = (float*)d_out;

    float *pw, *t, *pf, *agg, *fused, *dbuf, *ybuf, *adp, *seg, *seg2, *cnt;
    float *sum, *sumsq, *scale, *bias, *part, *gmax;
    cudaGetSymbolAddress((void**)&pw, g_pw);
    cudaGetSymbolAddress((void**)&t, g_t);
    cudaGetSymbolAddress((void**)&pf, g_pf);
    cudaGetSymbolAddress((void**)&agg, g_agg);
    cudaGetSymbolAddress((void**)&fused, g_fused);
    cudaGetSymbolAddress((void**)&dbuf, g_dbuf);
    cudaGetSymbolAddress((void**)&ybuf, g_ybuf);
    cudaGetSymbolAddress((void**)&adp, g_adp);
    cudaGetSymbolAddress((void**)&seg, g_seg);
    cudaGetSymbolAddress((void**)&seg2, g_seg2);
    cudaGetSymbolAddress((void**)&cnt, g_cnt);
    cudaGetSymbolAddress((void**)&sum, g_sum);
    cudaGetSymbolAddress((void**)&sumsq, g_sumsq);
    cudaGetSymbolAddress((void**)&scale, g_scale);
    cudaGetSymbolAddress((void**)&bias, g_bias);
    cudaGetSymbolAddress((void**)&part, g_part);
    cudaGetSymbolAddress((void**)&gmax, g_gmax);

    const int EB = 256;
    const int EG = NC / EB;

    auto bn_pipeline = [&](const float* X, const float* gamma, const float* beta) {
        cudaMemsetAsync(sum, 0, CH * sizeof(float), 0);
        cudaMemsetAsync(sumsq, 0, CH * sizeof(float), 0);
        colstats<<<NV / 128, 128>>>(X, sum, sumsq);
        bn_finalize<<<1, 128>>>(sum, sumsq, gamma, beta, scale, bias);
    };

    cudaMemsetAsync(agg, 0, (size_t)NC * sizeof(float), 0);
    adp_kernel<<<NV / 8, 256>>>(feat, adaptive_w, adp);

    for (int i = 0; i < 3; i++) {
        const int* cl = clusters + (size_t)i * NV;
        // pw = lrelu(bn(feat @ lw_w[i]))
        gemm128<<<512, 256>>>(feat, lw_w + (size_t)i * CH * CH, pw, 0);
        bn_pipeline(pw, lw_gamma + i * CH, lw_beta + i * CH);
        bn_act<<<EG, EB>>>(pw, scale, bias, nullptr, pw, 0);
        // per-cluster centering
        cudaMemsetAsync(cnt, 0, NSEGS * sizeof(float), 0);
        cudaMemsetAsync(seg, 0, (size_t)NSEGS * CH * sizeof(float), 0);
        seg_count<<<NV / 256, 256>>>(cl, cnt);
        seg_sum<<<EG, EB>>>(pw, cl, seg);
        sub_segmean<<<EG, EB>>>(pw, seg, cnt, cl);
        // attention logits -> exp(global-max-shifted) -> per-cluster normalize
        gemm128<<<512, 256>>>(pw, w_w + (size_t)i * CH * CH, t, 0);
        rmax1<<<1024, 256>>>(t, part);
        rmax2<<<1, 256>>>(part, gmax);
        cudaMemsetAsync(seg, 0, (size_t)NSEGS * CH * sizeof(float), 0);
        exp_seg<<<EG, EB>>>(t, gmax, cl, seg);
        // pf = lrelu(bn(feat @ proj_w[i])) * weights ; segment-sum ; agg accumulate
        gemm128<<<512, 256>>>(feat, proj_w + (size_t)i * CH * CH, pf, 0);
        bn_pipeline(pf, proj_gamma + i * CH, proj_beta + i * CH);
        bn_act<<<EG, EB>>>(pf, scale, bias, nullptr, pf, 0);
        cudaMemsetAsync(seg2, 0, (size_t)NSEGS * CH * sizeof(float), 0);
        wmul_seg<<<EG, EB>>>(pf, t, seg, cl, seg2);
        agg_acc<<<EG, EB>>>(agg, adp, i, seg2, cl);
    }

    // f_last = lrelu(bn(feat @ proj_w[3]))
    gemm128<<<512, 256>>>(feat, proj_w + (size_t)3 * CH * CH, pf, 0);
    bn_pipeline(pf, proj_gamma + 3 * CH, proj_beta + 3 * CH);
    bn_act<<<EG, EB>>>(pf, scale, bias, nullptr, pf, 0);

    // fused = lrelu(bn([f_last, agg] @ fuse_w)) + feat
    gemm128<<<512, 256>>>(pf, fuse_w, t, 0);
    gemm128<<<512, 256>>>(agg, fuse_w + (size_t)CH * CH, t, 1);
    bn_pipeline(t, fuse_gamma, fuse_beta);
    bn_act<<<EG, EB>>>(t, scale, bias, feat, fused, 1);

    // conv1 -> bn1 -> lrelu
    sconv128<<<512, 256>>>(fused, nbr, conv1_w, ybuf);
    bn_pipeline(ybuf, bn1_gamma, bn1_beta);
    bn_act<<<EG, EB>>>(ybuf, scale, bias, nullptr, dbuf, 0);

    // conv2 -> bn2 (+ residual) -> lrelu
    sconv128<<<512, 256>>>(dbuf, nbr, conv2_w, ybuf);
    bn_pipeline(ybuf, bn2_gamma, bn2_beta);
    bn_act<<<EG, EB>>>(ybuf, scale, bias, fused, out, 2);
}